// round 5
// baseline (speedup 1.0000x reference)
#include <cuda_runtime.h>
#include <cuda_fp16.h>
#include <cuda_bf16.h>
#include <cstdint>

#define TT 8        // timesteps (B*T)
#define FIN 64      // in features
#define HC 128      // H*C
#define NMAX 50016
#define EMAX 460000
#define NEG_SLOPE 0.2f

// bf16 smem tiles, padded rows (72 = 64+8 halves -> conflict-free pair loads)
#define XP 72
#define KP 72
// layout (bf16 counts): Xh[64*XP] Xl[64*XP] Wth[128*KP] Wtl[128*KP]
#define OFF_XH 0
#define OFF_XL (64 * XP)
#define OFF_WH (2 * 64 * XP)
#define OFF_WL (2 * 64 * XP + 128 * KP)
#define GEMM_SMEM ((2 * 64 * XP + 2 * 128 * KP) * 2)   // 55296 bytes

// ---- scratch (device globals; no cudaMalloc allowed) ----
__device__ int    g_deg[NMAX];
__device__ int    g_off[NMAX + 1];
__device__ int    g_cur[NMAX];
__device__ int    g_csr_src[EMAX];
__device__ int    g_csr_dst[EMAX];
__device__ __half g_xl[(size_t)TT * NMAX * HC];   // fp16, ~102 MB
__device__ float  g_as[(size_t)NMAX * TT * 2];    // [n][t][h]
__device__ float  g_ad[(size_t)NMAX * TT * 2];
__device__ float2 g_ex[(size_t)TT * EMAX];        // [t][csr_pos], ~29 MB

// ---------------- CSR build ----------------
__global__ void k_zero_deg(int N) {
    int i = blockIdx.x * blockDim.x + threadIdx.x;
    if (i < N) g_deg[i] = 0;
}

__global__ void k_count(const int* __restrict__ dst, int E) {
    int e = blockIdx.x * blockDim.x + threadIdx.x;
    if (e < E) atomicAdd(&g_deg[dst[e]], 1);
}

__global__ void k_scan(int N) {
    __shared__ int warp_sums[32];
    __shared__ int s_running;
    int tid = threadIdx.x, lane = tid & 31, wid = tid >> 5;
    if (tid == 0) { s_running = 0; g_off[0] = 0; }
    __syncthreads();
    for (int base = 0; base < N; base += 1024) {
        int i = base + tid;
        int v = (i < N) ? g_deg[i] : 0;
        int x = v;
        #pragma unroll
        for (int o = 1; o < 32; o <<= 1) {
            int y = __shfl_up_sync(0xffffffffu, x, o);
            if (lane >= o) x += y;
        }
        if (lane == 31) warp_sums[wid] = x;
        __syncthreads();
        if (wid == 0) {
            int ws = warp_sums[lane];
            #pragma unroll
            for (int o = 1; o < 32; o <<= 1) {
                int y = __shfl_up_sync(0xffffffffu, ws, o);
                if (lane >= o) ws += y;
            }
            warp_sums[lane] = ws;
        }
        __syncthreads();
        int prefix = s_running + (wid > 0 ? warp_sums[wid - 1] : 0) + x;
        if (i < N) {
            g_off[i + 1] = prefix;
            g_cur[i] = prefix - v;
        }
        __syncthreads();
        if (tid == 0) s_running += warp_sums[31];
        __syncthreads();
    }
}

__global__ void k_fill(const int* __restrict__ src, const int* __restrict__ dst, int E) {
    int e = blockIdx.x * blockDim.x + threadIdx.x;
    if (e < E) {
        int d = dst[e];
        int pos = atomicAdd(&g_cur[d], 1);
        g_csr_src[pos] = src[e];
        g_csr_dst[pos] = d;
    }
}

// ---------------- split-bf16 (3-MMA) tensor-core GEMM + fused scores + fp16 xl ----------------
__device__ __forceinline__ void mma16(float* d, unsigned int a0, unsigned int a1,
                                      unsigned int a2, unsigned int a3,
                                      unsigned int b0, unsigned int b1) {
    asm volatile(
        "mma.sync.aligned.m16n8k16.row.col.f32.bf16.bf16.f32 "
        "{%0,%1,%2,%3},{%4,%5,%6,%7},{%8,%9},{%0,%1,%2,%3};"
        : "+f"(d[0]), "+f"(d[1]), "+f"(d[2]), "+f"(d[3])
        : "r"(a0), "r"(a1), "r"(a2), "r"(a3), "r"(b0), "r"(b1));
}

// block 128 thr (4 warps); tile: 64 nodes x 128 cols, K=64.
// warp (wid): rows (wid&1)*32..+31, cols (wid>>1)*64..+63 (one head).
__global__ __launch_bounds__(128, 4) void k_gemm(const float* __restrict__ h,
                                                 const float* __restrict__ W,
                                                 const float* __restrict__ att_src,
                                                 const float* __restrict__ att_dst,
                                                 int N) {
    extern __shared__ __nv_bfloat16 smem[];
    __nv_bfloat16* Xh  = smem + OFF_XH;   // [64][XP] row-major (node, k)
    __nv_bfloat16* Xl  = smem + OFF_XL;
    __nv_bfloat16* Wth = smem + OFF_WH;   // [128][KP] (col, k) -- transposed W
    __nv_bfloat16* Wtl = smem + OFF_WL;
    int t = blockIdx.y;
    int n0 = blockIdx.x * 64;
    int tid = threadIdx.x;

    // load + split W (64x128) into transposed bf16 hi/lo smem
    #pragma unroll
    for (int i = 0; i < 16; i++) {
        int idx = tid + i * 128;            // 0..2047 float4s
        int k = idx >> 5, c4 = idx & 31;
        float4 v = ((const float4*)W)[idx];
        float vv[4] = {v.x, v.y, v.z, v.w};
        #pragma unroll
        for (int j = 0; j < 4; j++) {
            int col = c4 * 4 + j;
            __nv_bfloat16 bh = __float2bfloat16_rn(vv[j]);
            Wth[col * KP + k] = bh;
            Wtl[col * KP + k] = __float2bfloat16_rn(vv[j] - __bfloat162float(bh));
        }
    }
    // load + split X tile (64x64)
    #pragma unroll
    for (int i = 0; i < 8; i++) {
        int idx = tid + i * 128;            // 0..1023 float4s
        int row = idx >> 4, c4 = idx & 15;
        int n = n0 + row;
        float4 v = make_float4(0.f, 0.f, 0.f, 0.f);
        if (n < N) v = *(const float4*)(h + ((size_t)n * TT + t) * FIN + c4 * 4);
        float vv[4] = {v.x, v.y, v.z, v.w};
        #pragma unroll
        for (int j = 0; j < 4; j++) {
            int k = c4 * 4 + j;
            __nv_bfloat16 bh = __float2bfloat16_rn(vv[j]);
            Xh[row * XP + k] = bh;
            Xl[row * XP + k] = __float2bfloat16_rn(vv[j] - __bfloat162float(bh));
        }
    }
    __syncthreads();

    int wid = tid >> 5, lane = tid & 31;
    int R = (wid & 1) * 32;
    int CB = (wid >> 1) * 64;
    int p = lane >> 2, q = lane & 3;

    float acc[2][8][4];
    #pragma unroll
    for (int rt = 0; rt < 2; rt++)
        #pragma unroll
        for (int nt = 0; nt < 8; nt++)
            #pragma unroll
            for (int c = 0; c < 4; c++) acc[rt][nt][c] = 0.f;

    #pragma unroll
    for (int kt = 0; kt < 4; kt++) {        // k16 steps
        int k0 = kt * 16 + q * 2;
        unsigned int ah[2][4], al[2][4];
        #pragma unroll
        for (int rt = 0; rt < 2; rt++) {
            int r0 = R + rt * 16 + p;
            ah[rt][0] = *(unsigned int*)(Xh + r0 * XP + k0);
            ah[rt][1] = *(unsigned int*)(Xh + (r0 + 8) * XP + k0);
            ah[rt][2] = *(unsigned int*)(Xh + r0 * XP + k0 + 8);
            ah[rt][3] = *(unsigned int*)(Xh + (r0 + 8) * XP + k0 + 8);
            al[rt][0] = *(unsigned int*)(Xl + r0 * XP + k0);
            al[rt][1] = *(unsigned int*)(Xl + (r0 + 8) * XP + k0);
            al[rt][2] = *(unsigned int*)(Xl + r0 * XP + k0 + 8);
            al[rt][3] = *(unsigned int*)(Xl + (r0 + 8) * XP + k0 + 8);
        }
        #pragma unroll
        for (int nt = 0; nt < 8; nt++) {
            int col = CB + nt * 8 + p;
            unsigned int bh0 = *(unsigned int*)(Wth + col * KP + k0);
            unsigned int bh1 = *(unsigned int*)(Wth + col * KP + k0 + 8);
            unsigned int bl0 = *(unsigned int*)(Wtl + col * KP + k0);
            unsigned int bl1 = *(unsigned int*)(Wtl + col * KP + k0 + 8);
            #pragma unroll
            for (int rt = 0; rt < 2; rt++) {
                mma16(acc[rt][nt], ah[rt][0], ah[rt][1], ah[rt][2], ah[rt][3], bh0, bh1);
                mma16(acc[rt][nt], ah[rt][0], ah[rt][1], ah[rt][2], ah[rt][3], bl0, bl1);
                mma16(acc[rt][nt], al[rt][0], al[rt][1], al[rt][2], al[rt][3], bh0, bh1);
            }
        }
    }

    // ---- fused attention scores (fp32 accumulators) ----
    int head = wid >> 1;
    float sa[16], da[16];
    #pragma unroll
    for (int nt = 0; nt < 8; nt++)
        #pragma unroll
        for (int j = 0; j < 2; j++) {
            int col = CB + nt * 8 + q * 2 + j;
            sa[nt * 2 + j] = __ldg(att_src + col);
            da[nt * 2 + j] = __ldg(att_dst + col);
        }
    #pragma unroll
    for (int rt = 0; rt < 2; rt++)
        #pragma unroll
        for (int half = 0; half < 2; half++) {
            float ps = 0.f, pd = 0.f;
            #pragma unroll
            for (int nt = 0; nt < 8; nt++) {
                ps = fmaf(acc[rt][nt][half * 2 + 0], sa[nt * 2 + 0], ps);
                ps = fmaf(acc[rt][nt][half * 2 + 1], sa[nt * 2 + 1], ps);
                pd = fmaf(acc[rt][nt][half * 2 + 0], da[nt * 2 + 0], pd);
                pd = fmaf(acc[rt][nt][half * 2 + 1], da[nt * 2 + 1], pd);
            }
            ps += __shfl_xor_sync(0xffffffffu, ps, 1);
            ps += __shfl_xor_sync(0xffffffffu, ps, 2);
            pd += __shfl_xor_sync(0xffffffffu, pd, 1);
            pd += __shfl_xor_sync(0xffffffffu, pd, 2);
            if (q == 0) {
                int n = n0 + R + rt * 16 + half * 8 + p;
                if (n < N) {
                    g_as[((size_t)n * TT + t) * 2 + head] = ps;
                    g_ad[((size_t)n * TT + t) * 2 + head] = pd;
                }
            }
        }

    // ---- stage fp16 tile in smem, then coalesced dump ----
    __syncthreads();                 // done reading tiles
    __half* XsH = (__half*)smem;     // 64 x 128 fp16 = 16 KB (fits in 54 KB)
    #pragma unroll
    for (int rt = 0; rt < 2; rt++)
        #pragma unroll
        for (int nt = 0; nt < 8; nt++)
            #pragma unroll
            for (int half = 0; half < 2; half++) {
                int row = R + rt * 16 + half * 8 + p;
                int col = CB + nt * 8 + q * 2;
                __half2 hv = __floats2half2_rn(acc[rt][nt][half * 2 + 0],
                                               acc[rt][nt][half * 2 + 1]);
                *(__half2*)(XsH + row * HC + col) = hv;
            }
    __syncthreads();
    {
        __half* dstp = g_xl + ((size_t)t * N + n0) * HC;
        const uint4* s4 = (const uint4*)XsH;
        #pragma unroll
        for (int i = 0; i < 8; i++) {
            int idx = tid + i * 128;         // 1024 x 16B = 16 KB
            int n = n0 + (idx >> 4);
            if (n < N) ((uint4*)dstp)[idx] = s4[idx];
        }
    }
}

// ---------------- per (t, csr-pos) edge exp weights ----------------
__global__ __launch_bounds__(256) void k_edge(int E, int N) {
    int pos = blockIdx.x * blockDim.x + threadIdx.x;
    int t = blockIdx.y;
    if (pos >= E) return;
    int s = g_csr_src[pos];
    int d = g_csr_dst[pos];
    float2 a = *(const float2*)(g_as + ((size_t)s * TT + t) * 2);
    float2 b = *(const float2*)(g_ad + ((size_t)d * TT + t) * 2);
    float x0 = a.x + b.x, x1 = a.y + b.y;
    x0 = x0 > 0.f ? x0 : NEG_SLOPE * x0;
    x1 = x1 > 0.f ? x1 : NEG_SLOPE * x1;
    // scores bounded (|x| << 80): exp without max-subtraction is overflow-safe
    g_ex[(size_t)t * E + pos] = make_float2(__expf(x0), __expf(x1));
}

// ---------------- aggregation ----------------
// one warp per (t, dst-node); 32 lanes x 4 ch; lanes 0-15 head0, 16-31 head1.
// 4-way unrolled edge loop: 4 independent gathers in flight (MLP=4).
__global__ __launch_bounds__(256) void k_agg(const float* __restrict__ bias,
                                             float* __restrict__ out, int N, int E) {
    int gw = (blockIdx.x * blockDim.x + threadIdx.x) >> 5;
    int lane = threadIdx.x & 31;
    if (gw >= TT * N) return;
    int t = gw / N, n = gw - t * N;

    const __half* xl = g_xl + (size_t)t * N * HC;
    const float2* exb = g_ex + (size_t)t * E;
    int s0 = g_off[n], s1 = g_off[n + 1];
    bool hh0 = lane < 16;
    unsigned int ch = lane * 4;

    float4 acc = make_float4(0.f, 0.f, 0.f, 0.f);
    float den = 0.f;
    int e = s0;
    for (; e + 4 <= s1; e += 4) {
        int i0 = __ldg(&g_csr_src[e + 0]);
        int i1 = __ldg(&g_csr_src[e + 1]);
        int i2 = __ldg(&g_csr_src[e + 2]);
        int i3 = __ldg(&g_csr_src[e + 3]);
        float2 w0 = __ldg(&exb[e + 0]);
        float2 w1 = __ldg(&exb[e + 1]);
        float2 w2 = __ldg(&exb[e + 2]);
        float2 w3 = __ldg(&exb[e + 3]);
        uint2 r0 = *(const uint2*)(xl + (size_t)i0 * HC + ch);
        uint2 r1 = *(const uint2*)(xl + (size_t)i1 * HC + ch);
        uint2 r2 = *(const uint2*)(xl + (size_t)i2 * HC + ch);
        uint2 r3 = *(const uint2*)(xl + (size_t)i3 * HC + ch);
        float e0 = hh0 ? w0.x : w0.y;
        float e1 = hh0 ? w1.x : w1.y;
        float e2 = hh0 ? w2.x : w2.y;
        float e3 = hh0 ? w3.x : w3.y;
        den += (e0 + e1) + (e2 + e3);
        float2 a01, a23;
        a01 = __half22float2(*(__half2*)&r0.x); a23 = __half22float2(*(__half2*)&r0.y);
        acc.x = fmaf(e0, a01.x, acc.x); acc.y = fmaf(e0, a01.y, acc.y);
        acc.z = fmaf(e0, a23.x, acc.z); acc.w = fmaf(e0, a23.y, acc.w);
        a01 = __half22float2(*(__half2*)&r1.x); a23 = __half22float2(*(__half2*)&r1.y);
        acc.x = fmaf(e1, a01.x, acc.x); acc.y = fmaf(e1, a01.y, acc.y);
        acc.z = fmaf(e1, a23.x, acc.z); acc.w = fmaf(e1, a23.y, acc.w);
        a01 = __half22float2(*(__half2*)&r2.x); a23 = __half22float2(*(__half2*)&r2.y);
        acc.x = fmaf(e2, a01.x, acc.x); acc.y = fmaf(e2, a01.y, acc.y);
        acc.z = fmaf(e2, a23.x, acc.z); acc.w = fmaf(e2, a23.y, acc.w);
        a01 = __half22float2(*(__half2*)&r3.x); a23 = __half22float2(*(__half2*)&r3.y);
        acc.x = fmaf(e3, a01.x, acc.x); acc.y = fmaf(e3, a01.y, acc.y);
        acc.z = fmaf(e3, a23.x, acc.z); acc.w = fmaf(e3, a23.y, acc.w);
    }
    for (; e < s1; e++) {
        int i0 = __ldg(&g_csr_src[e]);
        float2 w0 = __ldg(&exb[e]);
        uint2 r0 = *(const uint2*)(xl + (size_t)i0 * HC + ch);
        float e0 = hh0 ? w0.x : w0.y;
        den += e0;
        float2 a01 = __half22float2(*(__half2*)&r0.x);
        float2 a23 = __half22float2(*(__half2*)&r0.y);
        acc.x = fmaf(e0, a01.x, acc.x); acc.y = fmaf(e0, a01.y, acc.y);
        acc.z = fmaf(e0, a23.x, acc.z); acc.w = fmaf(e0, a23.y, acc.w);
    }
    float inv = 1.f / den;
    acc.x *= inv; acc.y *= inv; acc.z *= inv; acc.w *= inv;

    float px = __shfl_down_sync(0xffffffffu, acc.x, 16);
    float py = __shfl_down_sync(0xffffffffu, acc.y, 16);
    float pz = __shfl_down_sync(0xffffffffu, acc.z, 16);
    float pw = __shfl_down_sync(0xffffffffu, acc.w, 16);
    if (hh0) {
        float4 b4 = *(const float4*)(bias + lane * 4);
        float4 o4;
        o4.x = 0.5f * (acc.x + px) + b4.x;
        o4.y = 0.5f * (acc.y + py) + b4.y;
        o4.z = 0.5f * (acc.z + pz) + b4.z;
        o4.w = 0.5f * (acc.w + pw) + b4.w;
        o4.x = o4.x > 0.f ? o4.x : (__expf(o4.x) - 1.f);
        o4.y = o4.y > 0.f ? o4.y : (__expf(o4.y) - 1.f);
        o4.z = o4.z > 0.f ? o4.z : (__expf(o4.z) - 1.f);
        o4.w = o4.w > 0.f ? o4.w : (__expf(o4.w) - 1.f);
        *(float4*)(out + ((size_t)n * TT + t) * 64 + lane * 4) = o4;
    }
}

extern "C" void kernel_launch(void* const* d_in, const int* in_sizes, int n_in,
                              void* d_out, int out_size) {
    const float* h       = (const float*)d_in[0];
    const int*   src     = (const int*)d_in[1];
    const int*   dst     = (const int*)d_in[2];
    const float* W       = (const float*)d_in[3];
    const float* att_src = (const float*)d_in[4];
    const float* att_dst = (const float*)d_in[5];
    const float* bias    = (const float*)d_in[6];
    float* out = (float*)d_out;

    int E = in_sizes[1];
    int N = in_sizes[0] / (TT * FIN);
    if (N > NMAX) N = NMAX;
    if (E > EMAX) E = EMAX;

    cudaFuncSetAttribute(k_gemm, cudaFuncAttributeMaxDynamicSharedMemorySize, GEMM_SMEM);

    // CSR build (timestep-invariant)
    k_zero_deg<<<(N + 255) / 256, 256>>>(N);
    k_count<<<(E + 255) / 256, 256>>>(dst, E);
    k_scan<<<1, 1024>>>(N);
    k_fill<<<(E + 255) / 256, 256>>>(src, dst, E);

    // tensor-core GEMM + fused scores (all timesteps)
    dim3 ggrid((N + 63) / 64, TT);
    k_gemm<<<ggrid, 128, GEMM_SMEM>>>(h, W, att_src, att_dst, N);

    // per-edge exp weights, CSR order (all timesteps)
    dim3 egrid((E + 255) / 256, TT);
    k_edge<<<egrid, 256>>>(E, N);

    // aggregation (softmax + message passing + head mean + bias + elu)
    int total_warps = TT * N;
    int ablocks = (total_warps * 32 + 255) / 256;
    k_agg<<<ablocks, 256>>>(bias, out, N, E);
}